// round 4
// baseline (speedup 1.0000x reference)
#include <cuda_runtime.h>
#include <cuda_bf16.h>
#include <cstdint>
#include <math.h>

#define BB 4096
#define TT 200
#define EE 64

using u64 = unsigned long long;

// ---------------- device globals (no runtime allocation allowed) ----------------
__device__ int   g_mask_u8;                 // 1 if mask stored as 1-byte bools, 0 if int32
__device__ float g_att[(size_t)BB * TT];    // softmax attention weights [B,T]

// ---------------- packed fp32x2 helpers (Blackwell) ----------------
static __device__ __forceinline__ u64 pk2(float x, float y) {
    u64 r; asm("mov.b64 %0,{%1,%2};" : "=l"(r) : "f"(x), "f"(y)); return r;
}
static __device__ __forceinline__ float2 up2(u64 v) {
    float2 r; asm("mov.b64 {%0,%1},%2;" : "=f"(r.x), "=f"(r.y) : "l"(v)); return r;
}
static __device__ __forceinline__ void fma2(u64& d, u64 a, u64 b) {
    asm("fma.rn.f32x2 %0,%1,%2,%0;" : "+l"(d) : "l"(a), "l"(b));
}
static __device__ __forceinline__ float sigmoidf_(float x) {
    return 1.0f / (1.0f + __expf(-x));
}
static __device__ __forceinline__ void cp_async16(void* dst, const void* src) {
    unsigned s = (unsigned)__cvta_generic_to_shared(dst);
    asm volatile("cp.async.cg.shared.global [%0], [%1], 16;" :: "r"(s), "l"(src));
}

// ---------------- mask dtype detection ----------------
// int32 bools: every 4-byte word is 0 or 1. uint8 bools at ~50% density: the
// chance 512 words all have their top 3 bytes zero is ~(1/8)^512 ~ 0.
__global__ void detect_mask_kernel(const unsigned int* m) {
    if (threadIdx.x == 0) {
        int u8 = 0;
        for (int i = 0; i < 512; i++) {
            if (m[i] > 1u) { u8 = 1; break; }
        }
        g_mask_u8 = u8;
    }
}
static __device__ __forceinline__ int load_mask(const void* mp, size_t idx, int u8) {
    return u8 ? (int)(((const unsigned char*)mp)[idx] != 0)
              : (int)(((const int*)mp)[idx] != 0);
}

// =====================================================================
// Kernel 1: attention logits + softmax, one CTA per batch row.
// feat@aw1 = q@(A0+A2) + k@(A1-A2) + (q*k)@A3; q-part hoisted per-b.
// =====================================================================
__global__ __launch_bounds__(256, 2) void attn_kernel(
    const float* __restrict__ gru, const float* __restrict__ query,
    const void* __restrict__ maskp,
    const float* __restrict__ aw1, const float* __restrict__ ab1,
    const float* __restrict__ aw2, const float* __restrict__ ab2,
    const float* __restrict__ aw3, const float* __restrict__ ab3)
{
    extern __shared__ float sm[];
    float* q_s   = sm;              // 64
    float* qa_s  = sm + 64;         // 32
    float* Wk_s  = sm + 96;         // 64*32 = A1 - A2
    float* Wqk_s = Wk_s + 2048;     // 64*32 = A3
    float* aw2_s = Wqk_s + 2048;    // 512
    float* ab2_s = aw2_s + 512;     // 16
    float* aw3_s = ab2_s + 16;      // 16
    float* red_s = aw3_s + 16;      // 16
    float* Ks    = red_s + 16;      // 200*65 (pad 65 -> conflict-free per-t reads)

    int tid = threadIdx.x;
    int b   = blockIdx.x;
    int mu8 = g_mask_u8;

    if (tid < 64) q_s[tid] = query[(size_t)b * EE + tid];
    for (int i = tid; i < 2048; i += 256) {
        int e = i >> 5, j = i & 31;
        Wk_s[i]  = aw1[(64 + e) * 32 + j] - aw1[(128 + e) * 32 + j];
        Wqk_s[i] = aw1[(192 + e) * 32 + j];
    }
    for (int i = tid; i < 512; i += 256) aw2_s[i] = aw2[i];
    if (tid < 16) { ab2_s[tid] = ab2[tid]; aw3_s[tid] = aw3[tid]; }
    for (int i = tid; i < TT * 16; i += 256) {
        int row = i >> 4, c = (i & 15) * 4;
        float4 v = *(const float4*)(gru + ((size_t)b * TT + row) * EE + c);
        float* d = Ks + row * 65 + c;
        d[0] = v.x; d[1] = v.y; d[2] = v.z; d[3] = v.w;
    }
    __syncthreads();

    if (tid < 32) {  // qa = q @ (A0+A2) + ab1   (once per b)
        float s = ab1[tid];
        for (int e = 0; e < 64; e++)
            s += q_s[e] * (aw1[e * 32 + tid] + aw1[(128 + e) * 32 + tid]);
        qa_s[tid] = s;
    }
    __syncthreads();

    int t = tid;
    float lg = -3.0e38f;
    if (t < TT) {
        u64 acc[16];
        const u64* Wk2  = (const u64*)Wk_s;
        const u64* Wqk2 = (const u64*)Wqk_s;
        #pragma unroll
        for (int j = 0; j < 16; j++) acc[j] = pk2(qa_s[2 * j], qa_s[2 * j + 1]);
        const float* kr = Ks + t * 65;
        #pragma unroll 4
        for (int e = 0; e < 64; e++) {
            float kv = kr[e];
            float qk = q_s[e] * kv;
            u64 kv2 = pk2(kv, kv), qk2 = pk2(qk, qk);
            #pragma unroll
            for (int j = 0; j < 16; j++) {
                fma2(acc[j], kv2, Wk2[e * 16 + j]);
                fma2(acc[j], qk2, Wqk2[e * 16 + j]);
            }
        }
        float h1[32];
        #pragma unroll
        for (int j = 0; j < 16; j++) {
            float2 v = up2(acc[j]);
            h1[2 * j] = sigmoidf_(v.x); h1[2 * j + 1] = sigmoidf_(v.y);
        }
        u64 acc2[8];
        const u64* A22 = (const u64*)aw2_s;
        #pragma unroll
        for (int j = 0; j < 8; j++) acc2[j] = pk2(ab2_s[2 * j], ab2_s[2 * j + 1]);
        #pragma unroll
        for (int i = 0; i < 32; i++) {
            u64 hv = pk2(h1[i], h1[i]);
            #pragma unroll
            for (int j = 0; j < 8; j++) fma2(acc2[j], hv, A22[i * 8 + j]);
        }
        float lgt = ab3[0];
        #pragma unroll
        for (int j = 0; j < 8; j++) {
            float2 v = up2(acc2[j]);
            lgt += sigmoidf_(v.x) * aw3_s[2 * j] + sigmoidf_(v.y) * aw3_s[2 * j + 1];
        }
        int m = load_mask(maskp, (size_t)b * TT + t, mu8);
        lg = m ? lgt : -1.0e9f;
    }

    // ---- block softmax over 200 logits ----
    float v = lg;
    #pragma unroll
    for (int off = 16; off > 0; off >>= 1) v = fmaxf(v, __shfl_xor_sync(0xffffffffu, v, off));
    if ((tid & 31) == 0) red_s[tid >> 5] = v;
    __syncthreads();
    if (tid == 0) { float m = red_s[0]; for (int i = 1; i < 8; i++) m = fmaxf(m, red_s[i]); red_s[8] = m; }
    __syncthreads();
    float bmax = red_s[8];
    float ex = (t < TT) ? __expf(lg - bmax) : 0.0f;
    float s = ex;
    #pragma unroll
    for (int off = 16; off > 0; off >>= 1) s += __shfl_xor_sync(0xffffffffu, s, off);
    if ((tid & 31) == 0) red_s[tid >> 5] = s;
    __syncthreads();
    if (tid == 0) { float m = 0.0f; for (int i = 0; i < 8; i++) m += red_s[i]; red_s[9] = m; }
    __syncthreads();
    float inv = __frcp_rn(red_s[9]);
    if (t < TT) g_att[(size_t)b * TT + t] = ex * inv;
}

// =====================================================================
// Kernel 2: persistent GRU scan with xp = gru@W fused into each step.
// 128 CTAs x 128 threads, 32 rows/CTA. Warp w owns rows 8w..8w+7; lane
// owns e-columns {2*lane, 2*lane+1}. k-tiles double-buffered via cp.async.
// =====================================================================
__global__ __launch_bounds__(128, 1) void scan_kernel(
    const float* __restrict__ gru, const void* __restrict__ maskp,
    const float* __restrict__ W, const float* __restrict__ U,
    const float* __restrict__ bias, float* __restrict__ out)
{
    extern __shared__ float sm[];
    float* Ur = sm;                 // [64][66] each
    float* Uz = Ur + 64 * 66;
    float* Un = Uz + 64 * 66;
    float* Wr = Un + 64 * 66;
    float* Wz = Wr + 64 * 66;
    float* Wn = Wz + 64 * 66;
    float* hS   = Wn + 64 * 66;     // [32][68]
    float* kS   = hS + 32 * 68;     // [2][32][68]
    float* attS = kS + 2 * 32 * 68; // [2][32]
    float* mS   = attS + 64;        // [2][32]

    int tid = threadIdx.x, lane = tid & 31, wid = tid >> 5;
    int rb  = blockIdx.x * 32;
    int mu8 = g_mask_u8;

    for (int i = tid; i < 64 * 64; i += 128) {
        int k = i >> 6, e = i & 63;
        const float* wrow = W + k * 192;
        const float* urow = U + k * 192;
        Wr[k * 66 + e] = wrow[e];  Wz[k * 66 + e] = wrow[64 + e];  Wn[k * 66 + e] = wrow[128 + e];
        Ur[k * 66 + e] = urow[e];  Uz[k * 66 + e] = urow[64 + e];  Un[k * 66 + e] = urow[128 + e];
    }
    for (int i = tid; i < 32 * 68; i += 128) hS[i] = 0.0f;
    {   // k-tile for t = 0 (direct loads); thread tid fills quarter-row tid>>2
        int r = tid >> 2, c0 = (tid & 3) * 16;
        const float4* src = (const float4*)(gru + ((size_t)(rb + r) * TT) * EE + c0);
        float4* dst = (float4*)(kS + r * 68 + c0);
        dst[0] = src[0]; dst[1] = src[1]; dst[2] = src[2]; dst[3] = src[3];
    }
    if (tid < 32) {
        attS[tid] = g_att[(size_t)(rb + tid) * TT];
        mS[tid]   = load_mask(maskp, (size_t)(rb + tid) * TT, mu8) ? 1.0f : 0.0f;
    }
    __syncthreads();

    u64 br = *(const u64*)(bias + 2 * lane);
    u64 bz = *(const u64*)(bias + 64 + 2 * lane);
    u64 bn = *(const u64*)(bias + 128 + 2 * lane);
    int r0 = wid * 8;

    for (int t = 0; t < TT; t++) {
        int cur = t & 1, nxt = cur ^ 1;

        // prefetch k-tile for t+1 into the other buffer
        if (t + 1 < TT) {
            int r = tid >> 2, c0 = (tid & 3) * 16;
            const float* src = gru + ((size_t)(rb + r) * TT + (t + 1)) * EE + c0;
            float* dst = kS + nxt * 2176 + r * 68 + c0;
            cp_async16(dst,      src);
            cp_async16(dst + 4,  src + 4);
            cp_async16(dst + 8,  src + 8);
            cp_async16(dst + 12, src + 12);
            asm volatile("cp.async.commit_group;");
        }
        float aN = 0.0f, mN = 0.0f;
        if (t + 1 < TT && tid < 32) {
            aN = g_att[(size_t)(rb + tid) * TT + t + 1];
            mN = load_mask(maskp, (size_t)(rb + tid) * TT + t + 1, mu8) ? 1.0f : 0.0f;
        }

        u64 a1r[8], a1z[8], a1n[8], a2r[8], a2z[8], a2n[8];
        #pragma unroll
        for (int rr = 0; rr < 8; rr++) {
            a1r[rr] = br; a1z[rr] = bz; a1n[rr] = bn;
            a2r[rr] = 0ull; a2z[rr] = 0ull; a2n[rr] = 0ull;
        }
        const float* kc = kS + cur * 2176;
        #pragma unroll 2
        for (int k = 0; k < 64; k++) {
            u64 ur = *(const u64*)(Ur + k * 66 + 2 * lane);
            u64 uz = *(const u64*)(Uz + k * 66 + 2 * lane);
            u64 un = *(const u64*)(Un + k * 66 + 2 * lane);
            u64 wr = *(const u64*)(Wr + k * 66 + 2 * lane);
            u64 wz = *(const u64*)(Wz + k * 66 + 2 * lane);
            u64 wn = *(const u64*)(Wn + k * 66 + 2 * lane);
            #pragma unroll
            for (int rr = 0; rr < 8; rr++) {
                float hv = hS[(r0 + rr) * 68 + k];   // warp-uniform broadcast
                float kv = kc[(r0 + rr) * 68 + k];
                u64 h2 = pk2(hv, hv), k2 = pk2(kv, kv);
                fma2(a2r[rr], h2, ur); fma2(a2z[rr], h2, uz); fma2(a2n[rr], h2, un);
                fma2(a1r[rr], k2, wr); fma2(a1z[rr], k2, wz); fma2(a1n[rr], k2, wn);
            }
        }

        float2 hnew[8];
        #pragma unroll
        for (int rr = 0; rr < 8; rr++) {
            int row = r0 + rr;
            float2 xr = up2(a1r[rr]), xz = up2(a1z[rr]), xn = up2(a1n[rr]);
            float2 hr = up2(a2r[rr]), hz = up2(a2z[rr]), hn = up2(a2n[rr]);
            float av = attS[cur * 32 + row] * mS[cur * 32 + row];  // mask folded into zt
            float2 hold = *(const float2*)(hS + row * 68 + 2 * lane);
            float rg0 = sigmoidf_(xr.x + hr.x), rg1 = sigmoidf_(xr.y + hr.y);
            float zg0 = sigmoidf_(xz.x + hz.x), zg1 = sigmoidf_(xz.y + hz.y);
            float n0 = tanhf(xn.x + rg0 * hn.x), n1 = tanhf(xn.y + rg1 * hn.y);
            float zt0 = av * zg0, zt1 = av * zg1;
            hnew[rr] = make_float2(hold.x + zt0 * (n0 - hold.x),
                                   hold.y + zt1 * (n1 - hold.y));
        }

        if (t + 1 < TT) asm volatile("cp.async.wait_group 0;" ::: "memory");
        #pragma unroll
        for (int rr = 0; rr < 8; rr++)
            *(float2*)(hS + (r0 + rr) * 68 + 2 * lane) = hnew[rr];
        if (t + 1 < TT && tid < 32) {
            attS[nxt * 32 + tid] = aN;
            mS[nxt * 32 + tid]   = mN;
        }
        __syncthreads();
    }

    // write h_final [B, 64]
    #pragma unroll
    for (int rr = 0; rr < 8; rr++) {
        int row = r0 + rr;
        *(float2*)(out + (size_t)(rb + row) * EE + 2 * lane) =
            *(const float2*)(hS + row * 68 + 2 * lane);
    }
}

// =====================================================================
extern "C" void kernel_launch(void* const* d_in, const int* in_sizes, int n_in,
                              void* d_out, int out_size) {
    const float* gru   = (const float*)d_in[0];
    const float* query = (const float*)d_in[1];
    const void*  maskp = (const void*) d_in[2];
    const float* aw1   = (const float*)d_in[3];
    const float* ab1   = (const float*)d_in[4];
    const float* aw2   = (const float*)d_in[5];
    const float* ab2   = (const float*)d_in[6];
    const float* aw3   = (const float*)d_in[7];
    const float* ab3   = (const float*)d_in[8];
    const float* W     = (const float*)d_in[9];
    const float* U     = (const float*)d_in[10];
    const float* bias  = (const float*)d_in[11];
    float* out = (float*)d_out;

    const int attn_smem = (64 + 32 + 2048 + 2048 + 512 + 16 + 16 + 16 + TT * 65) * 4;
    const int scan_smem = (6 * 64 * 66 + 32 * 68 + 2 * 32 * 68 + 64 + 64) * 4;
    cudaFuncSetAttribute(attn_kernel, cudaFuncAttributeMaxDynamicSharedMemorySize, attn_smem);
    cudaFuncSetAttribute(scan_kernel, cudaFuncAttributeMaxDynamicSharedMemorySize, scan_smem);

    detect_mask_kernel<<<1, 32>>>((const unsigned int*)maskp);
    attn_kernel<<<BB, 256, attn_smem>>>(gru, query, maskp, aw1, ab1, aw2, ab2, aw3, ab3);
    scan_kernel<<<128, 128, scan_smem>>>(gru, maskp, W, U, bias, out);
}

// round 5
// speedup vs baseline: 1.0051x; 1.0051x over previous
#include <cuda_runtime.h>
#include <cuda_bf16.h>
#include <cstdint>
#include <math.h>

#define BB 4096
#define TT 200
#define EE 64

using u64 = unsigned long long;

// ---------------- device globals ----------------
__device__ float g_att[(size_t)BB * TT];    // softmax attention weights * mask, [B,T]

// ---------------- packed fp32x2 helpers (Blackwell) ----------------
static __device__ __forceinline__ u64 pk2(float x, float y) {
    u64 r; asm("mov.b64 %0,{%1,%2};" : "=l"(r) : "f"(x), "f"(y)); return r;
}
static __device__ __forceinline__ float2 up2(u64 v) {
    float2 r; asm("mov.b64 {%0,%1},%2;" : "=f"(r.x), "=f"(r.y) : "l"(v)); return r;
}
static __device__ __forceinline__ void fma2(u64& d, u64 a, u64 b) {
    asm("fma.rn.f32x2 %0,%1,%2,%0;" : "+l"(d) : "l"(a), "l"(b));
}
static __device__ __forceinline__ float sigmoidf_(float x) {
    return 1.0f / (1.0f + __expf(-x));
}
// accurate-enough tanh via __expf (err ~1e-6, handles saturation)
static __device__ __forceinline__ float tanhf_(float x) {
    float e2 = __expf(2.0f * x);
    return 1.0f - 2.0f / (e2 + 1.0f);
}
static __device__ __forceinline__ void cp_async16(void* dst, const void* src) {
    unsigned s = (unsigned)__cvta_generic_to_shared(dst);
    asm volatile("cp.async.cg.shared.global [%0], [%1], 16;" :: "r"(s), "l"(src));
}

static __device__ __forceinline__ int load_mask(const void* mp, size_t idx, int u8) {
    return u8 ? (int)(((const unsigned char*)mp)[idx] != 0)
              : (int)(((const int*)mp)[idx] != 0);
}

// =====================================================================
// Kernel 1: attention logits + softmax (mask folded in), one CTA per b.
// feat@aw1 = q@(A0+A2) + k@(A1-A2) + (q*k)@A3; q-part hoisted per-b.
// Writes g_att = softmax * mask  (exact: masked entries are 0).
// =====================================================================
__global__ __launch_bounds__(256, 2) void attn_kernel(
    const float* __restrict__ gru, const float* __restrict__ query,
    const void* __restrict__ maskp,
    const float* __restrict__ aw1, const float* __restrict__ ab1,
    const float* __restrict__ aw2, const float* __restrict__ ab2,
    const float* __restrict__ aw3, const float* __restrict__ ab3)
{
    extern __shared__ float sm[];
    float* q_s   = sm;              // 64
    float* qa_s  = sm + 64;         // 32
    float* Wk_s  = sm + 96;         // 64*32 = A1 - A2
    float* Wqk_s = Wk_s + 2048;     // 64*32 = A3
    float* aw2_s = Wqk_s + 2048;    // 512
    float* ab2_s = aw2_s + 512;     // 16
    float* aw3_s = ab2_s + 16;      // 16
    float* red_s = aw3_s + 16;      // 16 (reductions + mask-dtype flag @12)
    float* Ks    = red_s + 16;      // 200*65 (pad 65 -> conflict-free per-t reads)

    int tid = threadIdx.x;
    int b   = blockIdx.x;

    // inline warp-parallel mask dtype detection (warp 0)
    if (tid < 32) {
        const unsigned int* mw = (const unsigned int*)maskp;
        unsigned bad = 0;
        #pragma unroll
        for (int i = 0; i < 16; i++) bad |= (mw[tid * 16 + i] > 1u) ? 1u : 0u;
        unsigned any = __any_sync(0xffffffffu, bad);
        if (tid == 0) red_s[12] = any ? 1.0f : 0.0f;
    }

    if (tid < 64) q_s[tid] = query[(size_t)b * EE + tid];
    for (int i = tid; i < 2048; i += 256) {
        int e = i >> 5, j = i & 31;
        Wk_s[i]  = aw1[(64 + e) * 32 + j] - aw1[(128 + e) * 32 + j];
        Wqk_s[i] = aw1[(192 + e) * 32 + j];
    }
    for (int i = tid; i < 512; i += 256) aw2_s[i] = aw2[i];
    if (tid < 16) { ab2_s[tid] = ab2[tid]; aw3_s[tid] = aw3[tid]; }
    for (int i = tid; i < TT * 16; i += 256) {
        int row = i >> 4, c = (i & 15) * 4;
        float4 v = *(const float4*)(gru + ((size_t)b * TT + row) * EE + c);
        float* d = Ks + row * 65 + c;
        d[0] = v.x; d[1] = v.y; d[2] = v.z; d[3] = v.w;
    }
    __syncthreads();

    if (tid < 32) {  // qa = q @ (A0+A2) + ab1   (once per b)
        float s = ab1[tid];
        for (int e = 0; e < 64; e++)
            s += q_s[e] * (aw1[e * 32 + tid] + aw1[(128 + e) * 32 + tid]);
        qa_s[tid] = s;
    }
    __syncthreads();

    int mu8 = (red_s[12] != 0.0f);
    int t = tid;
    float lg = -3.0e38f;
    int mflag = 0;
    if (t < TT) {
        u64 acc[16];
        const ulonglong2* Wk4  = (const ulonglong2*)Wk_s;   // [e][8 pairs]
        const ulonglong2* Wqk4 = (const ulonglong2*)Wqk_s;
        #pragma unroll
        for (int j = 0; j < 16; j++) acc[j] = pk2(qa_s[2 * j], qa_s[2 * j + 1]);
        const float* kr = Ks + t * 65;
        #pragma unroll 4
        for (int e = 0; e < 64; e++) {
            float kv = kr[e];
            float qk = q_s[e] * kv;
            u64 kv2 = pk2(kv, kv), qk2 = pk2(qk, qk);
            #pragma unroll
            for (int j2 = 0; j2 < 8; j2++) {
                ulonglong2 wa = Wk4[e * 8 + j2];
                fma2(acc[2 * j2],     kv2, wa.x);
                fma2(acc[2 * j2 + 1], kv2, wa.y);
                ulonglong2 wb = Wqk4[e * 8 + j2];
                fma2(acc[2 * j2],     qk2, wb.x);
                fma2(acc[2 * j2 + 1], qk2, wb.y);
            }
        }
        // MLP2 accumulated on the fly (no h1 array)
        u64 acc2[8];
        const ulonglong2* A24 = (const ulonglong2*)aw2_s;   // [32 rows][4 pairs]
        #pragma unroll
        for (int j = 0; j < 8; j++) acc2[j] = pk2(ab2_s[2 * j], ab2_s[2 * j + 1]);
        #pragma unroll
        for (int j = 0; j < 16; j++) {
            float2 v = up2(acc[j]);
            float h0 = sigmoidf_(v.x), h1v = sigmoidf_(v.y);
            u64 ha = pk2(h0, h0), hb = pk2(h1v, h1v);
            #pragma unroll
            for (int j2 = 0; j2 < 4; j2++) {
                ulonglong2 wa = A24[(2 * j) * 4 + j2];
                fma2(acc2[2 * j2],     ha, wa.x);
                fma2(acc2[2 * j2 + 1], ha, wa.y);
                ulonglong2 wb = A24[(2 * j + 1) * 4 + j2];
                fma2(acc2[2 * j2],     hb, wb.x);
                fma2(acc2[2 * j2 + 1], hb, wb.y);
            }
        }
        float lgt = ab3[0];
        #pragma unroll
        for (int j = 0; j < 8; j++) {
            float2 v = up2(acc2[j]);
            lgt += sigmoidf_(v.x) * aw3_s[2 * j] + sigmoidf_(v.y) * aw3_s[2 * j + 1];
        }
        mflag = load_mask(maskp, (size_t)b * TT + t, mu8);
        lg = mflag ? lgt : -1.0e9f;
    }

    // ---- block softmax over 200 logits ----
    float v = lg;
    #pragma unroll
    for (int off = 16; off > 0; off >>= 1) v = fmaxf(v, __shfl_xor_sync(0xffffffffu, v, off));
    if ((tid & 31) == 0) red_s[tid >> 5] = v;
    __syncthreads();
    if (tid == 0) { float m = red_s[0]; for (int i = 1; i < 8; i++) m = fmaxf(m, red_s[i]); red_s[8] = m; }
    __syncthreads();
    float bmax = red_s[8];
    float ex = (t < TT) ? __expf(lg - bmax) : 0.0f;
    float s = ex;
    #pragma unroll
    for (int off = 16; off > 0; off >>= 1) s += __shfl_xor_sync(0xffffffffu, s, off);
    if ((tid & 31) == 0) red_s[tid >> 5] = s;
    __syncthreads();
    if (tid == 0) { float m = 0.0f; for (int i = 0; i < 8; i++) m += red_s[i]; red_s[9] = m; }
    __syncthreads();
    float inv = __frcp_rn(red_s[9]);
    if (t < TT) g_att[(size_t)b * TT + t] = ex * inv * (mflag ? 1.0f : 0.0f);
}

// =====================================================================
// Kernel 2: persistent GRU scan, xp = gru@W fused. 128 CTAs x 128 thr,
// 32 rows/CTA; warp w owns rows 8w..8w+7, lane owns e-pair {2l,2l+1}.
// h and k stored TRANSPOSED in smem (stride 36) so the k-loop fetches
// 8 rows with 2 broadcast LDS.128 each. h also lives in registers.
// =====================================================================
#define KT_S 36
__global__ __launch_bounds__(128, 1) void scan_kernel(
    const float* __restrict__ gru,
    const float* __restrict__ W, const float* __restrict__ U,
    const float* __restrict__ bias, float* __restrict__ out)
{
    extern __shared__ float sm[];
    float* Ur = sm;                 // [64][66] each
    float* Uz = Ur + 64 * 66;
    float* Un = Uz + 64 * 66;
    float* Wr = Un + 64 * 66;
    float* Wz = Wr + 64 * 66;
    float* Wn = Wz + 64 * 66;
    float* kT    = Wn + 64 * 66;    // [64][36] transposed k-tile
    float* hT    = kT + 64 * KT_S;  // [64][36] transposed h
    float* stage = hT + 64 * KT_S;  // [32][68] cp.async staging
    float* attS  = stage + 32 * 68; // [2][32]

    int tid = threadIdx.x, lane = tid & 31, wid = tid >> 5;
    int rb  = blockIdx.x * 32;

    // weights -> smem (gate-split, padded rows)
    for (int i = tid; i < 64 * 64; i += 128) {
        int k = i >> 6, e = i & 63;
        const float* wrow = W + k * 192;
        const float* urow = U + k * 192;
        Wr[k * 66 + e] = wrow[e];  Wz[k * 66 + e] = wrow[64 + e];  Wn[k * 66 + e] = wrow[128 + e];
        Ur[k * 66 + e] = urow[e];  Uz[k * 66 + e] = urow[64 + e];  Un[k * 66 + e] = urow[128 + e];
    }
    for (int i = tid; i < 64 * KT_S; i += 128) hT[i] = 0.0f;

    // k-tile for t = 0: direct loads, transposed store
    {
        int r = tid >> 2, c0 = (tid & 3) * 16;
        const float* src = gru + ((size_t)(rb + r) * TT) * EE + c0;
        #pragma unroll
        for (int q = 0; q < 4; q++) {
            float4 v = *(const float4*)(src + 4 * q);
            kT[(c0 + 4 * q + 0) * KT_S + r] = v.x;
            kT[(c0 + 4 * q + 1) * KT_S + r] = v.y;
            kT[(c0 + 4 * q + 2) * KT_S + r] = v.z;
            kT[(c0 + 4 * q + 3) * KT_S + r] = v.w;
        }
    }
    if (tid < 32) attS[tid] = g_att[(size_t)(rb + tid) * TT];
    __syncthreads();

    u64 br = *(const u64*)(bias + 2 * lane);
    u64 bz = *(const u64*)(bias + 64 + 2 * lane);
    u64 bn = *(const u64*)(bias + 128 + 2 * lane);
    int r0 = wid * 8;

    float2 hreg[8];
    #pragma unroll
    for (int rr = 0; rr < 8; rr++) hreg[rr] = make_float2(0.0f, 0.0f);

    for (int t = 0; t < TT; t++) {
        int cur = t & 1, nxt = cur ^ 1;

        // prefetch k-tile for t+1 into staging buffer
        if (t + 1 < TT) {
            int r = tid >> 2, c0 = (tid & 3) * 16;
            const float* src = gru + ((size_t)(rb + r) * TT + (t + 1)) * EE + c0;
            float* dst = stage + r * 68 + c0;
            cp_async16(dst,      src);
            cp_async16(dst + 4,  src + 4);
            cp_async16(dst + 8,  src + 8);
            cp_async16(dst + 12, src + 12);
            asm volatile("cp.async.commit_group;");
        }
        float aN = 0.0f;
        if (t + 1 < TT && tid < 32) aN = g_att[(size_t)(rb + tid) * TT + t + 1];

        u64 a1r[8], a1z[8], a1n[8], a2r[8], a2z[8], a2n[8];
        #pragma unroll
        for (int rr = 0; rr < 8; rr++) {
            a1r[rr] = br; a1z[rr] = bz; a1n[rr] = bn;
            a2r[rr] = 0ull; a2z[rr] = 0ull; a2n[rr] = 0ull;
        }
        #pragma unroll 2
        for (int k = 0; k < 64; k++) {
            // 8 rows of h and k via broadcast LDS.128
            float4 h03 = *(const float4*)(hT + k * KT_S + r0);
            float4 h47 = *(const float4*)(hT + k * KT_S + r0 + 4);
            float4 k03 = *(const float4*)(kT + k * KT_S + r0);
            float4 k47 = *(const float4*)(kT + k * KT_S + r0 + 4);
            u64 ur = *(const u64*)(Ur + k * 66 + 2 * lane);
            u64 uz = *(const u64*)(Uz + k * 66 + 2 * lane);
            u64 un = *(const u64*)(Un + k * 66 + 2 * lane);
            u64 wr = *(const u64*)(Wr + k * 66 + 2 * lane);
            u64 wz = *(const u64*)(Wz + k * 66 + 2 * lane);
            u64 wn = *(const u64*)(Wn + k * 66 + 2 * lane);
            float hv8[8] = {h03.x, h03.y, h03.z, h03.w, h47.x, h47.y, h47.z, h47.w};
            float kv8[8] = {k03.x, k03.y, k03.z, k03.w, k47.x, k47.y, k47.z, k47.w};
            #pragma unroll
            for (int rr = 0; rr < 8; rr++) {
                u64 h2 = pk2(hv8[rr], hv8[rr]);
                u64 k2 = pk2(kv8[rr], kv8[rr]);
                fma2(a2r[rr], h2, ur); fma2(a2z[rr], h2, uz); fma2(a2n[rr], h2, un);
                fma2(a1r[rr], k2, wr); fma2(a1z[rr], k2, wz); fma2(a1n[rr], k2, wn);
            }
        }

        __syncthreads();   // all warps done reading hT/kT of step t

        // epilogue: gates + state update (h in registers), write hT
        #pragma unroll
        for (int rr = 0; rr < 8; rr++) {
            int row = r0 + rr;
            float2 xr = up2(a1r[rr]), xz = up2(a1z[rr]), xn = up2(a1n[rr]);
            float2 hr = up2(a2r[rr]), hz = up2(a2z[rr]), hn = up2(a2n[rr]);
            float av = attS[cur * 32 + row];        // already mask-folded
            float2 hold = hreg[rr];
            float rg0 = sigmoidf_(xr.x + hr.x), rg1 = sigmoidf_(xr.y + hr.y);
            float zg0 = sigmoidf_(xz.x + hz.x), zg1 = sigmoidf_(xz.y + hz.y);
            float n0 = tanhf_(xn.x + rg0 * hn.x), n1 = tanhf_(xn.y + rg1 * hn.y);
            float zt0 = av * zg0, zt1 = av * zg1;
            float2 hnew = make_float2(hold.x + zt0 * (n0 - hold.x),
                                      hold.y + zt1 * (n1 - hold.y));
            hreg[rr] = hnew;
            hT[(2 * lane)     * KT_S + row] = hnew.x;
            hT[(2 * lane + 1) * KT_S + row] = hnew.y;
        }

        if (t + 1 < TT) {
            if (tid < 32) attS[nxt * 32 + tid] = aN;
            // transpose staged k-tile (each thread transposes its own cp.async region)
            asm volatile("cp.async.wait_group 0;" ::: "memory");
            int r = tid >> 2, c0 = (tid & 3) * 16;
            const float* srow = stage + r * 68 + c0;
            #pragma unroll
            for (int q = 0; q < 4; q++) {
                float4 v = *(const float4*)(srow + 4 * q);
                kT[(c0 + 4 * q + 0) * KT_S + r] = v.x;
                kT[(c0 + 4 * q + 1) * KT_S + r] = v.y;
                kT[(c0 + 4 * q + 2) * KT_S + r] = v.z;
                kT[(c0 + 4 * q + 3) * KT_S + r] = v.w;
            }
        }
        __syncthreads();   // hT/kT/attS ready for step t+1
    }

    // write h_final [B, 64] from registers
    #pragma unroll
    for (int rr = 0; rr < 8; rr++) {
        int row = r0 + rr;
        *(float2*)(out + (size_t)(rb + row) * EE + 2 * lane) = hreg[rr];
    }
}

// =====================================================================
extern "C" void kernel_launch(void* const* d_in, const int* in_sizes, int n_in,
                              void* d_out, int out_size) {
    const float* gru   = (const float*)d_in[0];
    const float* query = (const float*)d_in[1];
    const void*  maskp = (const void*) d_in[2];
    const float* aw1   = (const float*)d_in[3];
    const float* ab1   = (const float*)d_in[4];
    const float* aw2   = (const float*)d_in[5];
    const float* ab2   = (const float*)d_in[6];
    const float* aw3   = (const float*)d_in[7];
    const float* ab3   = (const float*)d_in[8];
    const float* W     = (const float*)d_in[9];
    const float* U     = (const float*)d_in[10];
    const float* bias  = (const float*)d_in[11];
    float* out = (float*)d_out;

    const int attn_smem = (64 + 32 + 2048 + 2048 + 512 + 16 + 16 + 16 + TT * 65) * 4;
    const int scan_smem = (6 * 64 * 66 + 2 * 64 * KT_S + 32 * 68 + 64) * 4;
    cudaFuncSetAttribute(attn_kernel, cudaFuncAttributeMaxDynamicSharedMemorySize, attn_smem);
    cudaFuncSetAttribute(scan_kernel, cudaFuncAttributeMaxDynamicSharedMemorySize, scan_smem);

    attn_kernel<<<BB, 256, attn_smem>>>(gru, query, maskp, aw1, ab1, aw2, ab2, aw3, ab3);
    scan_kernel<<<128, 128, scan_smem>>>(gru, W, U, bias, out);
}

// round 7
// speedup vs baseline: 1.1913x; 1.1852x over previous
#include <cuda_runtime.h>
#include <cuda_bf16.h>
#include <cstdint>
#include <math.h>

#define BB 4096
#define TT 200
#define EE 64

using u64 = unsigned long long;

// ---------------- device globals ----------------
__device__ float g_att[(size_t)BB * TT];            // softmax * mask, [B,T]
__device__ float g_xp[3ull * BB * TT * EE];         // xp = gru@W + b, [gate][b*T+t][e]
#define RT64 ((size_t)BB * TT * EE)

// ---------------- packed fp32x2 helpers (Blackwell) ----------------
static __device__ __forceinline__ u64 pk2(float x, float y) {
    u64 r; asm("mov.b64 %0,{%1,%2};" : "=l"(r) : "f"(x), "f"(y)); return r;
}
static __device__ __forceinline__ float2 up2(u64 v) {
    float2 r; asm("mov.b64 {%0,%1},%2;" : "=f"(r.x), "=f"(r.y) : "l"(v)); return r;
}
static __device__ __forceinline__ void fma2(u64& d, u64 a, u64 b) {
    asm("fma.rn.f32x2 %0,%1,%2,%0;" : "+l"(d) : "l"(a), "l"(b));
}
static __device__ __forceinline__ float sigmoidf_(float x) {
    return 1.0f / (1.0f + __expf(-x));
}
static __device__ __forceinline__ float tanhf_(float x) {
    float e2 = __expf(2.0f * x);
    return 1.0f - 2.0f / (e2 + 1.0f);
}
static __device__ __forceinline__ void cp_async16(void* dst, const void* src) {
    unsigned s = (unsigned)__cvta_generic_to_shared(dst);
    asm volatile("cp.async.cg.shared.global [%0], [%1], 16;" :: "r"(s), "l"(src));
}
static __device__ __forceinline__ int load_mask(const void* mp, size_t idx, int u8) {
    return u8 ? (int)(((const unsigned char*)mp)[idx] != 0)
              : (int)(((const int*)mp)[idx] != 0);
}

// =====================================================================
// Kernel 1: attention logits + softmax (mask folded in), one CTA per b.
// =====================================================================
__global__ __launch_bounds__(256, 2) void attn_kernel(
    const float* __restrict__ gru, const float* __restrict__ query,
    const void* __restrict__ maskp,
    const float* __restrict__ aw1, const float* __restrict__ ab1,
    const float* __restrict__ aw2, const float* __restrict__ ab2,
    const float* __restrict__ aw3, const float* __restrict__ ab3)
{
    extern __shared__ float sm[];
    float* q_s   = sm;              // 64
    float* qa_s  = sm + 64;         // 32
    float* Wk_s  = sm + 96;         // 64*32 = A1 - A2
    float* Wqk_s = Wk_s + 2048;     // 64*32 = A3
    float* aw2_s = Wqk_s + 2048;    // 512
    float* ab2_s = aw2_s + 512;     // 16
    float* aw3_s = ab2_s + 16;      // 16
    float* red_s = aw3_s + 16;      // 16 (reductions + mask-dtype flag @12)
    float* Ks    = red_s + 16;      // 200*65

    int tid = threadIdx.x;
    int b   = blockIdx.x;

    if (tid < 32) {   // warp-parallel mask dtype detection
        const unsigned int* mw = (const unsigned int*)maskp;
        unsigned bad = 0;
        #pragma unroll
        for (int i = 0; i < 16; i++) bad |= (mw[tid * 16 + i] > 1u) ? 1u : 0u;
        unsigned any = __any_sync(0xffffffffu, bad);
        if (tid == 0) red_s[12] = any ? 1.0f : 0.0f;
    }

    if (tid < 64) q_s[tid] = query[(size_t)b * EE + tid];
    for (int i = tid; i < 2048; i += 256) {
        int e = i >> 5, j = i & 31;
        Wk_s[i]  = aw1[(64 + e) * 32 + j] - aw1[(128 + e) * 32 + j];
        Wqk_s[i] = aw1[(192 + e) * 32 + j];
    }
    for (int i = tid; i < 512; i += 256) aw2_s[i] = aw2[i];
    if (tid < 16) { ab2_s[tid] = ab2[tid]; aw3_s[tid] = aw3[tid]; }
    for (int i = tid; i < TT * 16; i += 256) {
        int row = i >> 4, c = (i & 15) * 4;
        float4 v = *(const float4*)(gru + ((size_t)b * TT + row) * EE + c);
        float* d = Ks + row * 65 + c;
        d[0] = v.x; d[1] = v.y; d[2] = v.z; d[3] = v.w;
    }
    __syncthreads();

    if (tid < 32) {
        float s = ab1[tid];
        for (int e = 0; e < 64; e++)
            s += q_s[e] * (aw1[e * 32 + tid] + aw1[(128 + e) * 32 + tid]);
        qa_s[tid] = s;
    }
    __syncthreads();

    int mu8 = (red_s[12] != 0.0f);
    int t = tid;
    float lg = -3.0e38f;
    int mflag = 0;
    if (t < TT) {
        u64 acc[16];
        const ulonglong2* Wk4  = (const ulonglong2*)Wk_s;
        const ulonglong2* Wqk4 = (const ulonglong2*)Wqk_s;
        #pragma unroll
        for (int j = 0; j < 16; j++) acc[j] = pk2(qa_s[2 * j], qa_s[2 * j + 1]);
        const float* kr = Ks + t * 65;
        #pragma unroll 4
        for (int e = 0; e < 64; e++) {
            float kv = kr[e];
            float qk = q_s[e] * kv;
            u64 kv2 = pk2(kv, kv), qk2 = pk2(qk, qk);
            #pragma unroll
            for (int j2 = 0; j2 < 8; j2++) {
                ulonglong2 wa = Wk4[e * 8 + j2];
                fma2(acc[2 * j2],     kv2, wa.x);
                fma2(acc[2 * j2 + 1], kv2, wa.y);
                ulonglong2 wb = Wqk4[e * 8 + j2];
                fma2(acc[2 * j2],     qk2, wb.x);
                fma2(acc[2 * j2 + 1], qk2, wb.y);
            }
        }
        u64 acc2[8];
        const ulonglong2* A24 = (const ulonglong2*)aw2_s;
        #pragma unroll
        for (int j = 0; j < 8; j++) acc2[j] = pk2(ab2_s[2 * j], ab2_s[2 * j + 1]);
        #pragma unroll
        for (int j = 0; j < 16; j++) {
            float2 v = up2(acc[j]);
            float h0 = sigmoidf_(v.x), h1v = sigmoidf_(v.y);
            u64 ha = pk2(h0, h0), hb = pk2(h1v, h1v);
            #pragma unroll
            for (int j2 = 0; j2 < 4; j2++) {
                ulonglong2 wa = A24[(2 * j) * 4 + j2];
                fma2(acc2[2 * j2],     ha, wa.x);
                fma2(acc2[2 * j2 + 1], ha, wa.y);
                ulonglong2 wb = A24[(2 * j + 1) * 4 + j2];
                fma2(acc2[2 * j2],     hb, wb.x);
                fma2(acc2[2 * j2 + 1], hb, wb.y);
            }
        }
        float lgt = ab3[0];
        #pragma unroll
        for (int j = 0; j < 8; j++) {
            float2 v = up2(acc2[j]);
            lgt += sigmoidf_(v.x) * aw3_s[2 * j] + sigmoidf_(v.y) * aw3_s[2 * j + 1];
        }
        mflag = load_mask(maskp, (size_t)b * TT + t, mu8);
        lg = mflag ? lgt : -1.0e9f;
    }

    float v = lg;
    #pragma unroll
    for (int off = 16; off > 0; off >>= 1) v = fmaxf(v, __shfl_xor_sync(0xffffffffu, v, off));
    if ((tid & 31) == 0) red_s[tid >> 5] = v;
    __syncthreads();
    if (tid == 0) { float m = red_s[0]; for (int i = 1; i < 8; i++) m = fmaxf(m, red_s[i]); red_s[8] = m; }
    __syncthreads();
    float bmax = red_s[8];
    float ex = (t < TT) ? __expf(lg - bmax) : 0.0f;
    float s = ex;
    #pragma unroll
    for (int off = 16; off > 0; off >>= 1) s += __shfl_xor_sync(0xffffffffu, s, off);
    if ((tid & 31) == 0) red_s[tid >> 5] = s;
    __syncthreads();
    if (tid == 0) { float m = 0.0f; for (int i = 0; i < 8; i++) m += red_s[i]; red_s[9] = m; }
    __syncthreads();
    float inv = __frcp_rn(red_s[9]);
    if (t < TT) g_att[(size_t)b * TT + t] = ex * inv * (mflag ? 1.0f : 0.0f);
}

// =====================================================================
// Kernel 2: xp = gru@W + b  (gate-split), fully parallel GEMM.
// 3200 CTAs x 128 thr; CTA does 8 tiles of 32 rows, cp.async double-buffered.
// =====================================================================
#define XP_RPB 256
__global__ __launch_bounds__(128) void xp_kernel(
    const float* __restrict__ gru, const float* __restrict__ W,
    const float* __restrict__ bias)
{
    extern __shared__ float sm[];
    float* Wr = sm;                 // [64][66] each
    float* Wz = Wr + 64 * 66;
    float* Wn = Wz + 64 * 66;
    float* kS = Wn + 64 * 66;       // [2][32][68]

    int tid = threadIdx.x, lane = tid & 31, wid = tid >> 5;
    size_t row0 = (size_t)blockIdx.x * XP_RPB;

    for (int i = tid; i < 64 * 64; i += 128) {
        int k = i >> 6, e = i & 63;
        const float* wrow = W + k * 192;
        Wr[k * 66 + e] = wrow[e];
        Wz[k * 66 + e] = wrow[64 + e];
        Wn[k * 66 + e] = wrow[128 + e];
    }

    int r = tid >> 2, c0 = (tid & 3) * 16;
    {   // preload tile 0
        const float* src = gru + (row0 + r) * EE + c0;
        float* dst = kS + r * 68 + c0;
        cp_async16(dst, src); cp_async16(dst + 4, src + 4);
        cp_async16(dst + 8, src + 8); cp_async16(dst + 12, src + 12);
        asm volatile("cp.async.commit_group;");
    }

    u64 br = *(const u64*)(bias + 2 * lane);
    u64 bz = *(const u64*)(bias + 64 + 2 * lane);
    u64 bn = *(const u64*)(bias + 128 + 2 * lane);
    int r0 = wid * 8;

    for (int tile = 0; tile < XP_RPB / 32; tile++) {
        int cur = tile & 1, nxt = cur ^ 1;
        bool more = (tile + 1 < XP_RPB / 32);
        if (more) {
            const float* src = gru + (row0 + (tile + 1) * 32 + r) * EE + c0;
            float* dst = kS + nxt * 2176 + r * 68 + c0;
            cp_async16(dst, src); cp_async16(dst + 4, src + 4);
            cp_async16(dst + 8, src + 8); cp_async16(dst + 12, src + 12);
            asm volatile("cp.async.commit_group;");
            asm volatile("cp.async.wait_group 1;" ::: "memory");
        } else {
            asm volatile("cp.async.wait_group 0;" ::: "memory");
        }
        __syncthreads();

        u64 ar[8], az[8], an[8];
        #pragma unroll
        for (int rr = 0; rr < 8; rr++) { ar[rr] = br; az[rr] = bz; an[rr] = bn; }
        const float* kc = kS + cur * 2176;
        #pragma unroll 2
        for (int k = 0; k < 64; k++) {
            u64 wr = *(const u64*)(Wr + k * 66 + 2 * lane);
            u64 wz = *(const u64*)(Wz + k * 66 + 2 * lane);
            u64 wn = *(const u64*)(Wn + k * 66 + 2 * lane);
            #pragma unroll
            for (int rr = 0; rr < 8; rr++) {
                float kv = kc[(r0 + rr) * 68 + k];
                u64 k2 = pk2(kv, kv);
                fma2(ar[rr], k2, wr); fma2(az[rr], k2, wz); fma2(an[rr], k2, wn);
            }
        }
        #pragma unroll
        for (int rr = 0; rr < 8; rr++) {
            size_t row = row0 + tile * 32 + r0 + rr;
            *(u64*)(g_xp +            row * EE + 2 * lane) = ar[rr];
            *(u64*)(g_xp + RT64     + row * EE + 2 * lane) = az[rr];
            *(u64*)(g_xp + 2 * RT64 + row * EE + 2 * lane) = an[rr];
        }
        __syncthreads();
    }
}

// =====================================================================
// Kernel 3: GRU scan (h@U only; xp precomputed). 128 CTAs x 256 thr,
// 32 rows/CTA, warp w owns rows 4w..4w+3 (2 warps/SMSP), lane = e-pair.
// =====================================================================
#define HT_S 36
__global__ __launch_bounds__(256, 1) void scan_kernel(
    const float* __restrict__ U, float* __restrict__ out)
{
    extern __shared__ float sm[];
    float* Ur = sm;                 // [64][66] each
    float* Uz = Ur + 64 * 66;
    float* Un = Uz + 64 * 66;
    float* hT   = Un + 64 * 66;     // [64][36]
    float* attS = hT + 64 * HT_S;   // [2][32]

    int tid = threadIdx.x, lane = tid & 31, wid = tid >> 5;
    int rb  = blockIdx.x * 32;

    for (int i = tid; i < 64 * 64; i += 256) {
        int k = i >> 6, e = i & 63;
        const float* urow = U + k * 192;
        Ur[k * 66 + e] = urow[e];
        Uz[k * 66 + e] = urow[64 + e];
        Un[k * 66 + e] = urow[128 + e];
    }
    for (int i = tid; i < 64 * HT_S; i += 256) hT[i] = 0.0f;
    if (tid < 32) attS[tid] = g_att[(size_t)(rb + tid) * TT];
    __syncthreads();

    int r0 = wid * 4;
    float2 hreg[4];
    #pragma unroll
    for (int rr = 0; rr < 4; rr++) hreg[rr] = make_float2(0.0f, 0.0f);

    u64 xcr[4], xcz[4], xcn[4];
    #pragma unroll
    for (int rr = 0; rr < 4; rr++) {
        size_t row = ((size_t)(rb + r0 + rr) * TT) * EE + 2 * lane;   // t = 0
        xcr[rr] = *(const u64*)(g_xp + row);
        xcz[rr] = *(const u64*)(g_xp + RT64 + row);
        xcn[rr] = *(const u64*)(g_xp + 2 * RT64 + row);
    }

    for (int t = 0; t < TT; t++) {
        int cur = t & 1, nxt = cur ^ 1;

        u64 xnr[4], xnz[4], xnn[4];
        float aN = 0.0f;
        if (t + 1 < TT) {
            #pragma unroll
            for (int rr = 0; rr < 4; rr++) {
                size_t row = ((size_t)(rb + r0 + rr) * TT + (t + 1)) * EE + 2 * lane;
                xnr[rr] = *(const u64*)(g_xp + row);
                xnz[rr] = *(const u64*)(g_xp + RT64 + row);
                xnn[rr] = *(const u64*)(g_xp + 2 * RT64 + row);
            }
            if (tid < 32) aN = g_att[(size_t)(rb + tid) * TT + t + 1];
        }

        u64 a2r[4], a2z[4], a2n[4];
        #pragma unroll
        for (int rr = 0; rr < 4; rr++) { a2r[rr] = 0ull; a2z[rr] = 0ull; a2n[rr] = 0ull; }

        #pragma unroll 4
        for (int k = 0; k < 64; k++) {
            float4 h03 = *(const float4*)(hT + k * HT_S + r0);   // broadcast LDS.128
            u64 ur = *(const u64*)(Ur + k * 66 + 2 * lane);
            u64 uz = *(const u64*)(Uz + k * 66 + 2 * lane);
            u64 un = *(const u64*)(Un + k * 66 + 2 * lane);
            float hv4[4] = {h03.x, h03.y, h03.z, h03.w};
            #pragma unroll
            for (int rr = 0; rr < 4; rr++) {
                u64 h2 = pk2(hv4[rr], hv4[rr]);
                fma2(a2r[rr], h2, ur); fma2(a2z[rr], h2, uz); fma2(a2n[rr], h2, un);
            }
        }

        __syncthreads();   // all warps done reading hT of step t

        #pragma unroll
        for (int rr = 0; rr < 4; rr++) {
            int row = r0 + rr;
            float2 xr = up2(xcr[rr]), xz = up2(xcz[rr]), xn = up2(xcn[rr]);
            float2 hr = up2(a2r[rr]), hz = up2(a2z[rr]), hn = up2(a2n[rr]);
            float av = attS[cur * 32 + row];      // mask already folded
            float2 hold = hreg[rr];
            float rg0 = sigmoidf_(xr.x + hr.x), rg1 = sigmoidf_(xr.y + hr.y);
            float zg0 = sigmoidf_(xz.x + hz.x), zg1 = sigmoidf_(xz.y + hz.y);
            float n0 = tanhf_(xn.x + rg0 * hn.x), n1 = tanhf_(xn.y + rg1 * hn.y);
            float zt0 = av * zg0, zt1 = av * zg1;
            hreg[rr] = make_float2(hold.x + zt0 * (n0 - hold.x),
                                   hold.y + zt1 * (n1 - hold.y));
        }
        // transposed write: thread owns all 4 rows of its e-pair -> 2x STS.128
        {
            float4 vx = make_float4(hreg[0].x, hreg[1].x, hreg[2].x, hreg[3].x);
            float4 vy = make_float4(hreg[0].y, hreg[1].y, hreg[2].y, hreg[3].y);
            *(float4*)(hT + (2 * lane)     * HT_S + r0) = vx;
            *(float4*)(hT + (2 * lane + 1) * HT_S + r0) = vy;
        }
        if (t + 1 < TT) {
            if (tid < 32) attS[nxt * 32 + tid] = aN;
            #pragma unroll
            for (int rr = 0; rr < 4; rr++) {
                xcr[rr] = xnr[rr]; xcz[rr] = xnz[rr]; xcn[rr] = xnn[rr];
            }
        }
        __syncthreads();   // hT/attS ready for step t+1
    }

    #pragma unroll
    for (int rr = 0; rr < 4; rr++) {
        int row = r0 + rr;
        *(float2*)(out + (size_t)(rb + row) * EE + 2 * lane) = hreg[rr];
    }
}

// =====================================================================
extern "C" void kernel_launch(void* const* d_in, const int* in_sizes, int n_in,
                              void* d_out, int out_size) {
    const float* gru   = (const float*)d_in[0];
    const float* query = (const float*)d_in[1];
    const void*  maskp = (const void*) d_in[2];
    const float* aw1   = (const float*)d_in[3];
    const float* ab1   = (const float*)d_in[4];
    const float* aw2   = (const float*)d_in[5];
    const float* ab2   = (const float*)d_in[6];
    const float* aw3   = (const float*)d_in[7];
    const float* ab3   = (const float*)d_in[8];
    const float* W     = (const float*)d_in[9];
    const float* U     = (const float*)d_in[10];
    const float* bias  = (const float*)d_in[11];
    float* out = (float*)d_out;

    const int attn_smem = (64 + 32 + 2048 + 2048 + 512 + 16 + 16 + 16 + TT * 65) * 4;
    const int xp_smem   = (3 * 64 * 66 + 2 * 32 * 68) * 4;
    const int scan_smem = (3 * 64 * 66 + 64 * HT_S + 64) * 4;
    cudaFuncSetAttribute(attn_kernel, cudaFuncAttributeMaxDynamicSharedMemorySize, attn_smem);
    cudaFuncSetAttribute(xp_kernel,   cudaFuncAttributeMaxDynamicSharedMemorySize, xp_smem);
    cudaFuncSetAttribute(scan_kernel, cudaFuncAttributeMaxDynamicSharedMemorySize, scan_smem);

    attn_kernel<<<BB, 256, attn_smem>>>(gru, query, maskp, aw1, ab1, aw2, ab2, aw3, ab3);
    xp_kernel<<<(BB * TT) / XP_RPB, 128, xp_smem>>>(gru, W, bias);
    scan_kernel<<<128, 256, scan_smem>>>(U, out);
}